// round 1
// baseline (speedup 1.0000x reference)
#include <cuda_runtime.h>
#include <math.h>

// ---------------------------------------------------------------------------
// ReversedAttention, restructured:
//   S_b  = sum_{n unmasked} key_n (x) value_n          (big GEMM 1, fp32)
//   u_b  = sum_{n unmasked} key_n ; w_b = sum value_n ; c_b = count
//   KtV  = Wk S Wv^T + (Wk u) bv^T + bk (Wv w + c bv)^T   (D x D, tiny)
//   aw   = softmax_d( KtV / sqrt(8) )
//   M_b  = Wq^T aw ;  r_b = bq^T aw
//   out  = query @ M_b + r_b                           (big GEMM 2, fp32)
// ---------------------------------------------------------------------------

#define NB 8
#define NN 8192
#define DD 256
#define NSPLIT 8      // stage-1 split over N
#define NS2 32        // vector-sum split over N

// ------------------------- device scratch (static, no allocs) --------------
__device__ float d_Spart[NSPLIT * NB * DD * DD];   // 16 MB
__device__ float d_S[NB * DD * DD];
__device__ float d_T1[NB * DD * DD];
__device__ float d_P[NB * DD * DD];                // pre-softmax then aw
__device__ float d_M[NB * DD * DD];
__device__ float d_Upart[NS2 * NB * DD];
__device__ float d_Wpart[NS2 * NB * DD];
__device__ float d_Cpart[NS2 * NB];
__device__ float d_u[NB * DD];
__device__ float d_w[NB * DD];
__device__ float d_cc[NB];
__device__ float d_kv1[NB * DD];
__device__ float d_kv2[NB * DD];
__device__ float d_r[NB * DD];
__device__ int   g_mask_mode;   // 0 = 4-byte elements, 1 = 1-byte elements

// ------------------------- mask handling -----------------------------------
// The bool mask may arrive as int32/float32 (4-byte) or int8/uint8 (1-byte).
// Detect by scanning the first 16384 32-bit words: packed bytes produce word
// values outside {0,1,0x3F800000}; 4-byte encodings do not.  ~10% True
// density over >=16384 scanned elements makes misclassification prob ~0.
__global__ void detect_mask_kernel(const unsigned int* __restrict__ mw) {
    __shared__ int hasByte;
    if (threadIdx.x == 0) hasByte = 0;
    __syncthreads();
    int local = 0;
    for (int i = threadIdx.x; i < 16384; i += blockDim.x) {
        unsigned v = mw[i];
        if (v > 1u && v != 0x3F800000u) local = 1;
    }
    if (local) atomicOr(&hasByte, 1);
    __syncthreads();
    if (threadIdx.x == 0) g_mask_mode = hasByte ? 1 : 0;
}

__device__ __forceinline__ float maskmul(const void* m, long i, int mode) {
    unsigned v = (mode == 0) ? ((const unsigned int*)m)[i]
                             : (unsigned)(((const unsigned char*)m)[i]);
    return v ? 0.0f : 1.0f;   // True = padded -> multiplier 0
}

// ------------------------- masked column sums u, w, c -----------------------
__global__ void uvw_part_kernel(const float* __restrict__ key,
                                const float* __restrict__ value,
                                const void* __restrict__ mask) {
    int b = blockIdx.x, sp = blockIdx.y, d = threadIdx.x;
    int mode = g_mask_mode;
    const int chunk = NN / NS2;                  // 256
    long nbase = (long)b * NN + (long)sp * chunk;
    float su = 0.f, sw = 0.f, cnt = 0.f;
    for (int n = 0; n < chunk; n++) {
        float mm = maskmul(mask, nbase + n, mode);
        su += mm * key  [(nbase + n) * DD + d];
        sw += mm * value[(nbase + n) * DD + d];
        if (d == 0) cnt += mm;
    }
    d_Upart[(sp * NB + b) * DD + d] = su;
    d_Wpart[(sp * NB + b) * DD + d] = sw;
    if (d == 0) d_Cpart[sp * NB + b] = cnt;
}

__global__ void uvw_reduce_kernel() {
    int b = blockIdx.x, d = threadIdx.x;
    float su = 0.f, sw = 0.f;
    for (int sp = 0; sp < NS2; sp++) {
        su += d_Upart[(sp * NB + b) * DD + d];
        sw += d_Wpart[(sp * NB + b) * DD + d];
    }
    d_u[b * DD + d] = su;
    d_w[b * DD + d] = sw;
    if (d == 0) {
        float c = 0.f;
        for (int sp = 0; sp < NS2; sp++) c += d_Cpart[sp * NB + b];
        d_cc[b] = c;
    }
}

// ------------------------- stage 1: S = key_masked^T @ value ---------------
// 128x128 tile, 256 threads, 8x8 per thread, packed f32x2 FMA.
__global__ __launch_bounds__(256) void stage1_kernel(
    const float* __restrict__ key, const float* __restrict__ value,
    const void* __restrict__ mask)
{
    __shared__ float As[16][132];   // [k][d]  (key, masked)
    __shared__ float Bs[16][132];   // [k][e]  (value)

    int t  = threadIdx.x;
    int b  = blockIdx.z >> 3;
    int sp = blockIdx.z & 7;
    int d0 = blockIdx.x * 128, e0 = blockIdx.y * 128;
    int mode = g_mask_mode;

    const int chunk = NN / NSPLIT;  // 1024
    long nbase = (long)b * NN + (long)sp * chunk;
    const float* kb = key   + nbase * DD;
    const float* vb = value + nbase * DD;

    int td = t & 15, te = t >> 4;

    unsigned long long acc[32];
    #pragma unroll
    for (int i = 0; i < 32; i++) acc[i] = 0ull;

    for (int kt = 0; kt < chunk; kt += 16) {
        #pragma unroll
        for (int h = 0; h < 2; h++) {
            int idx = t * 4 + h * 1024;
            int row = idx >> 7, col = idx & 127;
            float mm = maskmul(mask, nbase + kt + row, mode);
            float4 a4 = *(const float4*)(kb + (long)(kt + row) * DD + d0 + col);
            a4.x *= mm; a4.y *= mm; a4.z *= mm; a4.w *= mm;
            *(float4*)&As[row][col] = a4;
            *(float4*)&Bs[row][col] =
                *(const float4*)(vb + (long)(kt + row) * DD + e0 + col);
        }
        __syncthreads();
        #pragma unroll
        for (int k = 0; k < 16; k++) {
            float4 a0 = *(const float4*)&As[k][td * 8];
            float4 a1 = *(const float4*)&As[k][td * 8 + 4];
            float av[8] = {a0.x, a0.y, a0.z, a0.w, a1.x, a1.y, a1.z, a1.w};
            unsigned long long bp[4];
            #pragma unroll
            for (int c = 0; c < 4; c++)
                bp[c] = *(const unsigned long long*)&Bs[k][te * 8 + c * 2];
            #pragma unroll
            for (int r = 0; r < 8; r++) {
                unsigned long long ad;
                unsigned ai = __float_as_uint(av[r]);
                asm("mov.b64 %0, {%1, %1};" : "=l"(ad) : "r"(ai));
                #pragma unroll
                for (int c = 0; c < 4; c++)
                    asm("fma.rn.f32x2 %0, %1, %2, %0;"
                        : "+l"(acc[r * 4 + c]) : "l"(ad), "l"(bp[c]));
            }
        }
        __syncthreads();
    }

    float* out = d_Spart + ((long)(sp * NB + b) << 16);
    #pragma unroll
    for (int r = 0; r < 8; r++) {
        int d = d0 + td * 8 + r;
        #pragma unroll
        for (int c = 0; c < 4; c++)
            *(unsigned long long*)&out[(long)d * DD + e0 + te * 8 + c * 2] =
                acc[r * 4 + c];
    }
}

__global__ void s_reduce_kernel() {
    long i = (long)blockIdx.x * 256 + threadIdx.x;   // 0 .. 8*65536-1
    int b = (int)(i >> 16);
    int j = (int)(i & 65535);
    float s = 0.f;
    #pragma unroll
    for (int sp = 0; sp < NSPLIT; sp++)
        s += d_Spart[((long)(sp * NB + b) << 16) + j];
    d_S[((long)b << 16) + j] = s;
}

// ------------------------- kv vectors: kv1 = Wk u, kv2 = Wv w + c bv -------
__global__ void kv_kernel(const float* __restrict__ Wk,
                          const float* __restrict__ Wv,
                          const float* __restrict__ bv) {
    int b = blockIdx.x, d = threadIdx.x;
    __shared__ float su[DD], sw[DD];
    su[d] = d_u[b * DD + d];
    sw[d] = d_w[b * DD + d];
    __syncthreads();
    float s1 = 0.f, s2 = 0.f;
    for (int i = 0; i < DD; i++) {
        s1 = fmaf(Wk[(long)d * DD + i], su[i], s1);
        s2 = fmaf(Wv[(long)d * DD + i], sw[i], s2);
    }
    d_kv1[b * DD + d] = s1;
    d_kv2[b * DD + d] = s2 + d_cc[b] * bv[d];
}

// ------------------------- small batched 256x256x256 GEMM ------------------
// C_b = op(A_b) @ op(B_b); optional epilogue (C + x1*y1^T + x2*y2^T)*scale
template<bool TA, bool TB, bool EPI>
__global__ __launch_bounds__(128) void sgemm_k(
    const float* __restrict__ A, long sA,
    const float* __restrict__ B, long sB,
    float* __restrict__ C,
    const float* __restrict__ x1, int sx1,
    const float* __restrict__ y1, int sy1,
    const float* __restrict__ x2, int sx2,
    const float* __restrict__ y2, int sy2,
    float scale)
{
    __shared__ float As[16][36];   // [k][d]
    __shared__ float Bs[16][68];   // [k][e]
    int t = threadIdx.x;
    int b = blockIdx.z;
    int d0 = blockIdx.x * 32, e0 = blockIdx.y * 64;
    const float* Ab = A + (long)b * sA;
    const float* Bb = B + (long)b * sB;
    int td = t & 7, te = t >> 3;

    float acc[4][4];
    #pragma unroll
    for (int r = 0; r < 4; r++)
        #pragma unroll
        for (int c = 0; c < 4; c++) acc[r][c] = 0.f;

    for (int kt = 0; kt < DD; kt += 16) {
        if (TA) {
            int row = t >> 3, col = (t & 7) * 4;   // [k][d] tile, direct
            *(float4*)&As[row][col] =
                *(const float4*)&Ab[(long)(kt + row) * DD + d0 + col];
        } else {
            int row = t >> 2, col = (t & 3) * 4;   // [d][k] tile, transpose
            float4 v = *(const float4*)&Ab[(long)(d0 + row) * DD + kt + col];
            As[col + 0][row] = v.x; As[col + 1][row] = v.y;
            As[col + 2][row] = v.z; As[col + 3][row] = v.w;
        }
        #pragma unroll
        for (int h = 0; h < 2; h++) {
            int idx = t * 4 + h * 512;
            if (TB) {
                int row = idx >> 4, col = idx & 15;   // [e][k] tile, transpose
                float4 v = *(const float4*)&Bb[(long)(e0 + row) * DD + kt + col];
                Bs[col + 0][row] = v.x; Bs[col + 1][row] = v.y;
                Bs[col + 2][row] = v.z; Bs[col + 3][row] = v.w;
            } else {
                int row = idx >> 6, col = idx & 63;   // [k][e] tile, direct
                *(float4*)&Bs[row][col] =
                    *(const float4*)&Bb[(long)(kt + row) * DD + e0 + col];
            }
        }
        __syncthreads();
        #pragma unroll
        for (int k = 0; k < 16; k++) {
            float4 a  = *(const float4*)&As[k][td * 4];
            float4 bb = *(const float4*)&Bs[k][te * 4];
            float av[4] = {a.x, a.y, a.z, a.w};
            float bv[4] = {bb.x, bb.y, bb.z, bb.w};
            #pragma unroll
            for (int r = 0; r < 4; r++)
                #pragma unroll
                for (int c = 0; c < 4; c++)
                    acc[r][c] = fmaf(av[r], bv[c], acc[r][c]);
        }
        __syncthreads();
    }

    float* Cb = C + ((long)b << 16);
    #pragma unroll
    for (int r = 0; r < 4; r++) {
        int d = d0 + td * 4 + r;
        #pragma unroll
        for (int c = 0; c < 4; c++) {
            int e = e0 + te * 4 + c;
            float v = acc[r][c];
            if (EPI)
                v = (v + x1[b * sx1 + d] * y1[b * sy1 + e]
                       + x2[b * sx2 + d] * y2[b * sy2 + e]) * scale;
            Cb[(long)d * DD + e] = v;
        }
    }
}

// ------------------------- softmax over d (in-place on d_P) ----------------
__global__ void softmax_kernel() {
    int b = blockIdx.x, ec = blockIdx.y;
    int tx = threadIdx.x, ty = threadIdx.y;      // (64, 4)
    float* Pb = d_P + ((long)b << 16);
    int e = ec * 64 + tx;
    __shared__ float red[4][64];

    float mx = -3.4e38f;
    for (int d = ty; d < DD; d += 4) mx = fmaxf(mx, Pb[(long)d * DD + e]);
    red[ty][tx] = mx;
    __syncthreads();
    mx = fmaxf(fmaxf(red[0][tx], red[1][tx]), fmaxf(red[2][tx], red[3][tx]));
    __syncthreads();

    float s = 0.f;
    for (int d = ty; d < DD; d += 4) {
        float ev = expf(Pb[(long)d * DD + e] - mx);
        Pb[(long)d * DD + e] = ev;
        s += ev;
    }
    red[ty][tx] = s;
    __syncthreads();
    float tot = red[0][tx] + red[1][tx] + red[2][tx] + red[3][tx];
    float inv = 1.0f / tot;
    for (int d = ty; d < DD; d += 4) Pb[(long)d * DD + e] *= inv;
}

// ------------------------- r = bq^T aw -------------------------------------
__global__ void rvec_kernel(const float* __restrict__ bq) {
    int b = blockIdx.x, e = threadIdx.x;
    const float* Pb = d_P + ((long)b << 16);
    float s = 0.f;
    for (int d = 0; d < DD; d++) s = fmaf(bq[d], Pb[(long)d * DD + e], s);
    d_r[b * DD + e] = s;
}

// ------------------------- stage 3: out = query @ M + r --------------------
__global__ __launch_bounds__(256) void stage3_kernel(
    const float* __restrict__ query, float* __restrict__ out)
{
    __shared__ float As[16][132];   // [k][n]  (query, transposed tile)
    __shared__ float Bs[16][132];   // [k][e]  (M)

    int t = threadIdx.x;
    int b = blockIdx.z;
    int n0 = blockIdx.x * 128, e0 = blockIdx.y * 128;

    const float* qb = query + (long)b * NN * DD;
    const float* Mb = d_M + ((long)b << 16);
    const float* rb = d_r + b * DD;

    int tn = t & 15, te = t >> 4;

    unsigned long long acc[32];
    #pragma unroll
    for (int i = 0; i < 32; i++) acc[i] = 0ull;

    for (int kt = 0; kt < DD; kt += 16) {
        #pragma unroll
        for (int h = 0; h < 2; h++) {
            int idx = t * 4 + h * 1024;
            int arow = idx >> 4, acol = idx & 15;   // acol in {0,4,8,12}
            float4 v = *(const float4*)&qb[(long)(n0 + arow) * DD + kt + acol];
            As[acol + 0][arow] = v.x; As[acol + 1][arow] = v.y;
            As[acol + 2][arow] = v.z; As[acol + 3][arow] = v.w;
            int brow = idx >> 7, bcol = idx & 127;
            *(float4*)&Bs[brow][bcol] =
                *(const float4*)&Mb[(long)(kt + brow) * DD + e0 + bcol];
        }
        __syncthreads();
        #pragma unroll
        for (int k = 0; k < 16; k++) {
            float4 a0 = *(const float4*)&As[k][tn * 8];
            float4 a1 = *(const float4*)&As[k][tn * 8 + 4];
            float av[8] = {a0.x, a0.y, a0.z, a0.w, a1.x, a1.y, a1.z, a1.w};
            unsigned long long bp[4];
            #pragma unroll
            for (int c = 0; c < 4; c++)
                bp[c] = *(const unsigned long long*)&Bs[k][te * 8 + c * 2];
            #pragma unroll
            for (int r = 0; r < 8; r++) {
                unsigned long long ad;
                unsigned ai = __float_as_uint(av[r]);
                asm("mov.b64 %0, {%1, %1};" : "=l"(ad) : "r"(ai));
                #pragma unroll
                for (int c = 0; c < 4; c++)
                    asm("fma.rn.f32x2 %0, %1, %2, %0;"
                        : "+l"(acc[r * 4 + c]) : "l"(ad), "l"(bp[c]));
            }
        }
        __syncthreads();
    }

    #pragma unroll
    for (int r = 0; r < 8; r++) {
        int n = n0 + tn * 8 + r;
        #pragma unroll
        for (int c = 0; c < 4; c++) {
            int e = e0 + te * 8 + c * 2;
            union { unsigned long long u; float2 f; } cv;
            cv.u = acc[r * 4 + c];
            float2 rv = *(const float2*)&rb[e];
            cv.f.x += rv.x; cv.f.y += rv.y;
            *(float2*)&out[((long)b * NN + n) * DD + e] = cv.f;
        }
    }
}

// ---------------------------------------------------------------------------
extern "C" void kernel_launch(void* const* d_in, const int* in_sizes, int n_in,
                              void* d_out, int out_size)
{
    const float* query = (const float*)d_in[0];
    const float* key   = (const float*)d_in[1];
    const float* value = (const float*)d_in[2];
    const void*  mask  = d_in[3];
    // need_weights scalar may or may not be materialized as an input
    int wo = (n_in >= 11 && in_sizes[4] == 1) ? 5 : 4;
    const float* Wq = (const float*)d_in[wo + 0];
    const float* bq = (const float*)d_in[wo + 1];
    const float* Wk = (const float*)d_in[wo + 2];
    const float* bk = (const float*)d_in[wo + 3];
    const float* Wv = (const float*)d_in[wo + 4];
    const float* bv = (const float*)d_in[wo + 5];
    float* out = (float*)d_out;

    float *pS, *pT1, *pP, *pM, *pkv1, *pkv2;
    cudaGetSymbolAddress((void**)&pS,   d_S);
    cudaGetSymbolAddress((void**)&pT1,  d_T1);
    cudaGetSymbolAddress((void**)&pP,   d_P);
    cudaGetSymbolAddress((void**)&pM,   d_M);
    cudaGetSymbolAddress((void**)&pkv1, d_kv1);
    cudaGetSymbolAddress((void**)&pkv2, d_kv2);

    const float inv_sqrt8 = 0.35355339059327373f;

    detect_mask_kernel<<<1, 256>>>((const unsigned int*)mask);
    uvw_part_kernel<<<dim3(NB, NS2), DD>>>(key, value, mask);
    uvw_reduce_kernel<<<NB, DD>>>();
    stage1_kernel<<<dim3(2, 2, NB * NSPLIT), 256>>>(key, value, mask);
    s_reduce_kernel<<<NB * DD * DD / 256, 256>>>();
    kv_kernel<<<NB, DD>>>(Wk, Wv, bv);
    // T1 = Wk @ S
    sgemm_k<false, false, false><<<dim3(8, 4, NB), 128>>>(
        Wk, 0, pS, (long)DD * DD, pT1,
        nullptr, 0, nullptr, 0, nullptr, 0, nullptr, 0, 1.0f);
    // P = (T1 @ Wv^T + kv1*bv^T + bk*kv2^T) / sqrt(8)
    sgemm_k<false, true, true><<<dim3(8, 4, NB), 128>>>(
        pT1, (long)DD * DD, Wv, 0, pP,
        pkv1, DD, bv, 0, bk, 0, pkv2, DD, inv_sqrt8);
    softmax_kernel<<<dim3(NB, 4), dim3(64, 4)>>>();
    rvec_kernel<<<NB, DD>>>(bq);
    // M = Wq^T @ aw
    sgemm_k<true, false, false><<<dim3(8, 4, NB), 128>>>(
        Wq, 0, pP, (long)DD * DD, pM,
        nullptr, 0, nullptr, 0, nullptr, 0, nullptr, 0, 1.0f);
    stage3_kernel<<<dim3(64, 2, NB), 256>>>(query, out);
}

// round 2
// speedup vs baseline: 1.0917x; 1.0917x over previous
#include <cuda_runtime.h>
#include <math.h>

// ---------------------------------------------------------------------------
// ReversedAttention, restructured:
//   S_b  = sum_{n unmasked} key_n (x) value_n          (big GEMM 1, fp32)
//   u_b  = masked key colsum ; w_b = value colsum ; c_b = count   (fused in GEMM1)
//   KtV  = Wk S Wv^T + (Wk u) bv^T + bk (Wv w + c bv)^T   (D x D, tiny)
//   aw   = softmax_d( KtV / sqrt(8) )
//   M_b  = Wq^T aw ;  r_b = bq^T aw
//   out  = query @ M_b + r_b                           (big GEMM 2, fp32)
// ---------------------------------------------------------------------------

#define NB 8
#define NN 8192
#define DD 256
#define NSPLIT 16     // stage-1 split over N
#define KT 16         // k-tile depth
#define STG 4         // cp.async pipeline stages

// ------------------------- device scratch (static, no allocs) --------------
__device__ float d_Spart[NSPLIT * NB * DD * DD];   // 32 MB
__device__ float d_S[NB * DD * DD];
__device__ float d_T1[NB * DD * DD];
__device__ float d_P[NB * DD * DD];
__device__ float d_M[NB * DD * DD];
__device__ float d_Upart[NSPLIT * NB * DD];
__device__ float d_Wpart[NSPLIT * NB * DD];
__device__ float d_Cpart[NSPLIT * NB];
__device__ float d_u[NB * DD];
__device__ float d_w[NB * DD];
__device__ float d_cc[NB];
__device__ float d_kv1[NB * DD];
__device__ float d_kv2[NB * DD];
__device__ float d_r[NB * DD];
__device__ int   g_mask_mode;   // 0 = 4-byte elements, 1 = 1-byte elements

// ------------------------- mask handling -----------------------------------
__global__ void detect_mask_kernel(const unsigned int* __restrict__ mw) {
    __shared__ int hasByte;
    if (threadIdx.x == 0) hasByte = 0;
    __syncthreads();
    int local = 0;
    for (int i = threadIdx.x; i < 16384; i += blockDim.x) {
        unsigned v = mw[i];
        if (v > 1u && v != 0x3F800000u) local = 1;
    }
    if (local) atomicOr(&hasByte, 1);
    __syncthreads();
    if (threadIdx.x == 0) g_mask_mode = hasByte ? 1 : 0;
}

__device__ __forceinline__ int mask_raw(const void* m, long i, int mode) {
    return (mode == 0) ? (((const unsigned int*)m)[i] != 0u)
                       : (((const unsigned char*)m)[i] != 0);
}

// ------------------------- cp.async helpers --------------------------------
__device__ __forceinline__ void cpa16(void* smem, const void* gmem) {
    unsigned sa = (unsigned)__cvta_generic_to_shared(smem);
    asm volatile("cp.async.cg.shared.global [%0], [%1], 16;"
                 :: "r"(sa), "l"(gmem));
}
__device__ __forceinline__ void cpa16z(void* smem, const void* gmem, int srcsz) {
    unsigned sa = (unsigned)__cvta_generic_to_shared(smem);
    asm volatile("cp.async.cg.shared.global [%0], [%1], 16, %2;"
                 :: "r"(sa), "l"(gmem), "r"(srcsz));
}
__device__ __forceinline__ void cpa_commit() {
    asm volatile("cp.async.commit_group;" ::: "memory");
}
__device__ __forceinline__ void cpa_wait2() {
    asm volatile("cp.async.wait_group 2;" ::: "memory");
}

// ------------------------- stage 1: S = key_masked^T @ value ---------------
// 128x128 tile, 256 threads, 8x8/thread, FFMA2, 4-stage cp.async pipeline.
// Mask applied via cp.async zero-fill (src-size 0 for padded rows).
// Diagonal blocks additionally produce masked key colsums (u) and value
// colsums (w); block (0,0) produces the unmasked count c.
__global__ __launch_bounds__(256, 2) void stage1_kernel(
    const float* __restrict__ key, const float* __restrict__ value,
    const void* __restrict__ mask)
{
    __shared__ float As[STG][KT][132];
    __shared__ float Bs[STG][KT][132];
    __shared__ float cntsh[KT];

    int t  = threadIdx.x;
    int b  = blockIdx.z >> 4;
    int sp = blockIdx.z & 15;
    int d0 = blockIdx.x * 128, e0 = blockIdx.y * 128;
    int diag  = (blockIdx.x == blockIdx.y);
    int zero0 = (d0 == 0 && e0 == 0);
    int mode = g_mask_mode;

    const int chunk = NN / NSPLIT;   // 512
    long nbase = (long)b * NN + (long)sp * chunk;
    const float* kb = key   + nbase * DD;
    const float* vb = value + nbase * DD;

    int td = t & 15, te = t >> 4;
    // copy mapping: chunks t and t+256 of 512 float4-chunks per array
    int r0 = t >> 5,         q0 = (t & 31) << 2;
    int r1 = (t + 256) >> 5, q1 = q0;

    auto issue = [&](int kt0, int s) {
        long n0r = nbase + kt0 + r0;
        long n1r = nbase + kt0 + r1;
        int sz0 = mask_raw(mask, n0r, mode) ? 0 : 16;
        int sz1 = mask_raw(mask, n1r, mode) ? 0 : 16;
        cpa16z(&As[s][r0][q0], kb + (long)(kt0 + r0) * DD + d0 + q0, sz0);
        cpa16z(&As[s][r1][q1], kb + (long)(kt0 + r1) * DD + d0 + q1, sz1);
        cpa16 (&Bs[s][r0][q0], vb + (long)(kt0 + r0) * DD + e0 + q0);
        cpa16 (&Bs[s][r1][q1], vb + (long)(kt0 + r1) * DD + e0 + q1);
        cpa_commit();
    };

    unsigned long long acc[32];
    #pragma unroll
    for (int i = 0; i < 32; i++) acc[i] = 0ull;
    float colsum = 0.f, cnt = 0.f;

    const int ntiles = chunk / KT;   // 32
    issue(0, 0); issue(KT, 1); issue(2 * KT, 2);

    for (int i = 0; i < ntiles; i++) {
        cpa_wait2();
        __syncthreads();
        if (i + 3 < ntiles) issue((i + 3) * KT, (i + 3) & 3);
        int s = i & 3;

        #pragma unroll
        for (int k = 0; k < KT; k++) {
            union { float4 f; unsigned long long u[2]; } b0, b1;
            b0.f = *(const float4*)&Bs[s][k][te * 8];
            b1.f = *(const float4*)&Bs[s][k][te * 8 + 4];
            float4 a0 = *(const float4*)&As[s][k][td * 8];
            float4 a1 = *(const float4*)&As[s][k][td * 8 + 4];
            float av[8] = {a0.x, a0.y, a0.z, a0.w, a1.x, a1.y, a1.z, a1.w};
            unsigned long long bp[4] = {b0.u[0], b0.u[1], b1.u[0], b1.u[1]};
            #pragma unroll
            for (int r = 0; r < 8; r++) {
                unsigned long long ad;
                unsigned ai = __float_as_uint(av[r]);
                asm("mov.b64 %0, {%1, %1};" : "=l"(ad) : "r"(ai));
                #pragma unroll
                for (int c = 0; c < 4; c++)
                    asm("fma.rn.f32x2 %0, %1, %2, %0;"
                        : "+l"(acc[r * 4 + c]) : "l"(ad), "l"(bp[c]));
            }
        }

        if (diag) {   // masked key colsum (As) / value colsum (Bs)
            int cc = t & 127;
            const float* col = (t < 128) ? &As[s][0][cc] : &Bs[s][0][cc];
            float sacc = 0.f;
            #pragma unroll
            for (int k = 0; k < KT; k++) sacc += col[k * 132];
            colsum += sacc;
        }
        if (zero0 && t < KT)
            cnt += mask_raw(mask, nbase + (long)i * KT + t, mode) ? 0.f : 1.f;
    }

    float* outp = d_Spart + ((long)(sp * NB + b) << 16);
    #pragma unroll
    for (int r = 0; r < 8; r++) {
        int d = d0 + td * 8 + r;
        #pragma unroll
        for (int c = 0; c < 4; c++)
            *(unsigned long long*)&outp[(long)d * DD + e0 + te * 8 + c * 2] =
                acc[r * 4 + c];
    }
    if (diag) {
        int cc = t & 127;
        if (t < 128) d_Upart[(sp * NB + b) * DD + d0 + cc] = colsum;
        else         d_Wpart[(sp * NB + b) * DD + e0 + cc] = colsum;
    }
    if (zero0) {
        if (t < KT) cntsh[t] = cnt;
        __syncthreads();
        if (t == 0) {
            float s = 0.f;
            #pragma unroll
            for (int k = 0; k < KT; k++) s += cntsh[k];
            d_Cpart[sp * NB + b] = s;
        }
    }
}

__global__ void s_reduce_kernel() {
    long i = (long)blockIdx.x * 256 + threadIdx.x;
    int b = (int)(i >> 16);
    int j = (int)(i & 65535);
    float s = 0.f;
    #pragma unroll
    for (int sp = 0; sp < NSPLIT; sp++)
        s += d_Spart[((long)(sp * NB + b) << 16) + j];
    d_S[((long)b << 16) + j] = s;
}

__global__ void uvw_reduce_kernel() {
    int b = blockIdx.x, d = threadIdx.x;
    float su = 0.f, sw = 0.f;
    #pragma unroll
    for (int sp = 0; sp < NSPLIT; sp++) {
        su += d_Upart[(sp * NB + b) * DD + d];
        sw += d_Wpart[(sp * NB + b) * DD + d];
    }
    d_u[b * DD + d] = su;
    d_w[b * DD + d] = sw;
    if (d == 0) {
        float c = 0.f;
        #pragma unroll
        for (int sp = 0; sp < NSPLIT; sp++) c += d_Cpart[sp * NB + b];
        d_cc[b] = c;
    }
}

// ------------------------- kv vectors: kv1 = Wk u, kv2 = Wv w + c bv -------
__global__ void kv_kernel(const float* __restrict__ Wk,
                          const float* __restrict__ Wv,
                          const float* __restrict__ bv) {
    int b = blockIdx.x, d = threadIdx.x;
    __shared__ float su[DD], sw[DD];
    su[d] = d_u[b * DD + d];
    sw[d] = d_w[b * DD + d];
    __syncthreads();
    float s1 = 0.f, s2 = 0.f;
    for (int i = 0; i < DD; i++) {
        s1 = fmaf(Wk[(long)d * DD + i], su[i], s1);
        s2 = fmaf(Wv[(long)d * DD + i], sw[i], s2);
    }
    d_kv1[b * DD + d] = s1;
    d_kv2[b * DD + d] = s2 + d_cc[b] * bv[d];
}

// ------------------------- small batched 256x256x256 GEMM ------------------
template<bool TA, bool TB, bool EPI>
__global__ __launch_bounds__(128) void sgemm_k(
    const float* __restrict__ A, long sA,
    const float* __restrict__ B, long sB,
    float* __restrict__ C,
    const float* __restrict__ x1, int sx1,
    const float* __restrict__ y1, int sy1,
    const float* __restrict__ x2, int sx2,
    const float* __restrict__ y2, int sy2,
    float scale)
{
    __shared__ float As[16][36];
    __shared__ float Bs[16][68];
    int t = threadIdx.x;
    int b = blockIdx.z;
    int d0 = blockIdx.x * 32, e0 = blockIdx.y * 64;
    const float* Ab = A + (long)b * sA;
    const float* Bb = B + (long)b * sB;
    int td = t & 7, te = t >> 3;

    float acc[4][4];
    #pragma unroll
    for (int r = 0; r < 4; r++)
        #pragma unroll
        for (int c = 0; c < 4; c++) acc[r][c] = 0.f;

    for (int kt = 0; kt < DD; kt += 16) {
        if (TA) {
            int row = t >> 3, col = (t & 7) * 4;
            *(float4*)&As[row][col] =
                *(const float4*)&Ab[(long)(kt + row) * DD + d0 + col];
        } else {
            int row = t >> 2, col = (t & 3) * 4;
            float4 v = *(const float4*)&Ab[(long)(d0 + row) * DD + kt + col];
            As[col + 0][row] = v.x; As[col + 1][row] = v.y;
            As[col + 2][row] = v.z; As[col + 3][row] = v.w;
        }
        #pragma unroll
        for (int h = 0; h < 2; h++) {
            int idx = t * 4 + h * 512;
            if (TB) {
                int row = idx >> 4, col = idx & 15;
                float4 v = *(const float4*)&Bb[(long)(e0 + row) * DD + kt + col];
                Bs[col + 0][row] = v.x; Bs[col + 1][row] = v.y;
                Bs[col + 2][row] = v.z; Bs[col + 3][row] = v.w;
            } else {
                int row = idx >> 6, col = idx & 63;
                *(float4*)&Bs[row][col] =
                    *(const float4*)&Bb[(long)(kt + row) * DD + e0 + col];
            }
        }
        __syncthreads();
        #pragma unroll
        for (int k = 0; k < 16; k++) {
            float4 a  = *(const float4*)&As[k][td * 4];
            float4 bb = *(const float4*)&Bs[k][te * 4];
            float av[4] = {a.x, a.y, a.z, a.w};
            float bv2[4] = {bb.x, bb.y, bb.z, bb.w};
            #pragma unroll
            for (int r = 0; r < 4; r++)
                #pragma unroll
                for (int c = 0; c < 4; c++)
                    acc[r][c] = fmaf(av[r], bv2[c], acc[r][c]);
        }
        __syncthreads();
    }

    float* Cb = C + ((long)b << 16);
    #pragma unroll
    for (int r = 0; r < 4; r++) {
        int d = d0 + td * 4 + r;
        #pragma unroll
        for (int c = 0; c < 4; c++) {
            int e = e0 + te * 4 + c;
            float v = acc[r][c];
            if (EPI)
                v = (v + x1[b * sx1 + d] * y1[b * sy1 + e]
                       + x2[b * sx2 + d] * y2[b * sy2 + e]) * scale;
            Cb[(long)d * DD + e] = v;
        }
    }
}

// ------------------------- softmax over d (in-place on d_P) ----------------
__global__ void softmax_kernel() {
    int b = blockIdx.x, ec = blockIdx.y;
    int tx = threadIdx.x, ty = threadIdx.y;      // (64, 4)
    float* Pb = d_P + ((long)b << 16);
    int e = ec * 64 + tx;
    __shared__ float red[4][64];

    float mx = -3.4e38f;
    for (int d = ty; d < DD; d += 4) mx = fmaxf(mx, Pb[(long)d * DD + e]);
    red[ty][tx] = mx;
    __syncthreads();
    mx = fmaxf(fmaxf(red[0][tx], red[1][tx]), fmaxf(red[2][tx], red[3][tx]));
    __syncthreads();

    float s = 0.f;
    for (int d = ty; d < DD; d += 4) {
        float ev = expf(Pb[(long)d * DD + e] - mx);
        Pb[(long)d * DD + e] = ev;
        s += ev;
    }
    red[ty][tx] = s;
    __syncthreads();
    float tot = red[0][tx] + red[1][tx] + red[2][tx] + red[3][tx];
    float inv = 1.0f / tot;
    for (int d = ty; d < DD; d += 4) Pb[(long)d * DD + e] *= inv;
}

// ------------------------- r = bq^T aw -------------------------------------
__global__ void rvec_kernel(const float* __restrict__ bq) {
    int b = blockIdx.x, e = threadIdx.x;
    const float* Pb = d_P + ((long)b << 16);
    float s = 0.f;
    for (int d = 0; d < DD; d++) s = fmaf(bq[d], Pb[(long)d * DD + e], s);
    d_r[b * DD + e] = s;
}

// ------------------------- stage 3: out = query @ M + r --------------------
// Register-double-buffered: prefetch tile i+1 from GMEM while computing i.
__global__ __launch_bounds__(256, 2) void stage3_kernel(
    const float* __restrict__ query, float* __restrict__ out)
{
    __shared__ float As[KT][132];   // [k][n]  (query, transposed)
    __shared__ float Bs[KT][132];   // [k][e]  (M)

    int t = threadIdx.x;
    int b = blockIdx.z;
    int n0 = blockIdx.x * 128, e0 = blockIdx.y * 128;

    const float* qb = query + (long)b * NN * DD;
    const float* Mb = d_M + ((long)b << 16);
    const float* rb = d_r + b * DD;

    int tn = t & 15, te = t >> 4;
    int ar = t & 127, acb = (t >> 7) * 8;       // A prefetch mapping
    int br0 = t >> 5,        bq0 = (t & 31) << 2;
    int br1 = (t >> 5) + 8;

    unsigned long long acc[32];
    #pragma unroll
    for (int i = 0; i < 32; i++) acc[i] = 0ull;

    float4 pa0 = *(const float4*)&qb[(long)(n0 + ar) * DD + acb];
    float4 pa1 = *(const float4*)&qb[(long)(n0 + ar) * DD + acb + 4];
    float4 pb0 = *(const float4*)&Mb[(long)br0 * DD + e0 + bq0];
    float4 pb1 = *(const float4*)&Mb[(long)br1 * DD + e0 + bq0];

    const int ntiles = DD / KT;   // 16
    for (int i = 0; i < ntiles; i++) {
        __syncthreads();   // previous compute done before overwriting smem
        As[acb + 0][ar] = pa0.x; As[acb + 1][ar] = pa0.y;
        As[acb + 2][ar] = pa0.z; As[acb + 3][ar] = pa0.w;
        As[acb + 4][ar] = pa1.x; As[acb + 5][ar] = pa1.y;
        As[acb + 6][ar] = pa1.z; As[acb + 7][ar] = pa1.w;
        *(float4*)&Bs[br0][bq0] = pb0;
        *(float4*)&Bs[br1][bq0] = pb1;
        __syncthreads();
        if (i + 1 < ntiles) {
            int kt = (i + 1) * KT;
            pa0 = *(const float4*)&qb[(long)(n0 + ar) * DD + kt + acb];
            pa1 = *(const float4*)&qb[(long)(n0 + ar) * DD + kt + acb + 4];
            pb0 = *(const float4*)&Mb[(long)(kt + br0) * DD + e0 + bq0];
            pb1 = *(const float4*)&Mb[(long)(kt + br1) * DD + e0 + bq0];
        }
        #pragma unroll
        for (int k = 0; k < KT; k++) {
            union { float4 f; unsigned long long u[2]; } b0, b1;
            b0.f = *(const float4*)&Bs[k][te * 8];
            b1.f = *(const float4*)&Bs[k][te * 8 + 4];
            float4 a0 = *(const float4*)&As[k][tn * 8];
            float4 a1 = *(const float4*)&As[k][tn * 8 + 4];
            float av[8] = {a0.x, a0.y, a0.z, a0.w, a1.x, a1.y, a1.z, a1.w};
            unsigned long long bp[4] = {b0.u[0], b0.u[1], b1.u[0], b1.u[1]};
            #pragma unroll
            for (int r = 0; r < 8; r++) {
                unsigned long long ad;
                unsigned ai = __float_as_uint(av[r]);
                asm("mov.b64 %0, {%1, %1};" : "=l"(ad) : "r"(ai));
                #pragma unroll
                for (int c = 0; c < 4; c++)
                    asm("fma.rn.f32x2 %0, %1, %2, %0;"
                        : "+l"(acc[r * 4 + c]) : "l"(ad), "l"(bp[c]));
            }
        }
    }

    #pragma unroll
    for (int r = 0; r < 8; r++) {
        int n = n0 + tn * 8 + r;
        #pragma unroll
        for (int c = 0; c < 4; c++) {
            int e = e0 + te * 8 + c * 2;
            union { unsigned long long u; float2 f; } cv;
            cv.u = acc[r * 4 + c];
            float2 rv = *(const float2*)&rb[e];
            cv.f.x += rv.x; cv.f.y += rv.y;
            *(float2*)&out[((long)b * NN + n) * DD + e] = cv.f;
        }
    }
}

// ---------------------------------------------------------------------------
extern "C" void kernel_launch(void* const* d_in, const int* in_sizes, int n_in,
                              void* d_out, int out_size)
{
    const float* query = (const float*)d_in[0];
    const float* key   = (const float*)d_in[1];
    const float* value = (const float*)d_in[2];
    const void*  mask  = d_in[3];
    int wo = (n_in >= 11 && in_sizes[4] == 1) ? 5 : 4;
    const float* Wq = (const float*)d_in[wo + 0];
    const float* bq = (const float*)d_in[wo + 1];
    const float* Wk = (const float*)d_in[wo + 2];
    const float* bk = (const float*)d_in[wo + 3];
    const float* Wv = (const float*)d_in[wo + 4];
    const float* bv = (const float*)d_in[wo + 5];
    float* out = (float*)d_out;

    float *pS, *pT1, *pP, *pM, *pkv1, *pkv2;
    cudaGetSymbolAddress((void**)&pS,   d_S);
    cudaGetSymbolAddress((void**)&pT1,  d_T1);
    cudaGetSymbolAddress((void**)&pP,   d_P);
    cudaGetSymbolAddress((void**)&pM,   d_M);
    cudaGetSymbolAddress((void**)&pkv1, d_kv1);
    cudaGetSymbolAddress((void**)&pkv2, d_kv2);

    const float inv_sqrt8 = 0.35355339059327373f;

    detect_mask_kernel<<<1, 256>>>((const unsigned int*)mask);
    stage1_kernel<<<dim3(2, 2, NB * NSPLIT), 256>>>(key, value, mask);
    s_reduce_kernel<<<NB * DD * DD / 256, 256>>>();
    uvw_reduce_kernel<<<NB, DD>>>();
    kv_kernel<<<NB, DD>>>(Wk, Wv, bv);
    // T1 = Wk @ S
    sgemm_k<false, false, false><<<dim3(8, 4, NB), 128>>>(
        Wk, 0, pS, (long)DD * DD, pT1,
        nullptr, 0, nullptr, 0, nullptr, 0, nullptr, 0, 1.0f);
    // P = (T1 @ Wv^T + kv1*bv^T + bk*kv2^T) / sqrt(8)
    sgemm_k<false, true, true><<<dim3(8, 4, NB), 128>>>(
        pT1, (long)DD * DD, Wv, 0, pP,
        pkv1, DD, bv, 0, bk, 0, pkv2, DD, inv_sqrt8);
    softmax_kernel<<<dim3(NB, 4), dim3(64, 4)>>>();
    rvec_kernel<<<NB, DD>>>(bq);
    // M = Wq^T @ aw
    sgemm_k<true, false, false><<<dim3(8, 4, NB), 128>>>(
        Wq, 0, pP, (long)DD * DD, pM,
        nullptr, 0, nullptr, 0, nullptr, 0, nullptr, 0, 1.0f);
    stage3_kernel<<<dim3(64, 2, NB), 256>>>(query, out);
}